// round 3
// baseline (speedup 1.0000x reference)
#include <cuda_runtime.h>
#include <cstddef>

#define BB 32
#define LL 1024
#define DD 64
#define QT 32          // queries per block
#define MC 64          // keys per chunk
#define NCH (LL/MC)    // 16 chunks
#define SDIM 1025      // padded score row stride (floats)
#define KSTR 17        // float4 stride for 68-float padded rows

__device__ __forceinline__ float neg_inf() { return __int_as_float(0xff800000); }

__device__ int g_mask_is_int32;

// Detect whether the mask buffer is int32 (bytes at offset%4!=0 all zero over
// the first 4KB) or 1-byte bool (random 0/1 -> ~50% nonzero at any offset).
__global__ void detect_mask_kernel(const unsigned char* __restrict__ m)
{
    if (threadIdx.x == 0 && blockIdx.x == 0) {
        int nz = 0;
        #pragma unroll 4
        for (int i = 0; i < 4096; i++) {
            if ((i & 3) != 0 && m[i] != 0) nz++;
        }
        g_mask_is_int32 = (nz == 0) ? 1 : 0;
    }
}

__global__ __launch_bounds__(256, 1)
void sdpa_rel_kernel(const float* __restrict__ qg,
                     const float* __restrict__ kg,
                     const float* __restrict__ vg,
                     const unsigned char* __restrict__ mg,
                     const float* __restrict__ pg,
                     const float* __restrict__ qpg,
                     float* __restrict__ out)
{
    extern __shared__ float smem[];
    float* s    = smem;                       // QT * SDIM scores
    float* q_s  = s + QT * SDIM;              // QT * 68
    float* qp_s = q_s + QT * 68;              // QT * 68
    float* kv_s = qp_s + QT * 68;             // MC * 68 (K, then reused for V)
    float* pd_s = kv_s + MC * 68;             // 96 * 68 (95 rows used)
    unsigned char* mk_s = (unsigned char*)(pd_s + 96 * 68); // 2048 bytes

    float4* q_s4  = (float4*)q_s;
    float4* qp_s4 = (float4*)qp_s;
    float4* kv_s4 = (float4*)kv_s;
    float4* pd_s4 = (float4*)pd_s;

    const int tid  = threadIdx.x;
    const int lane = tid & 31;
    const int w    = tid >> 5;
    const int t0   = blockIdx.x * QT;
    const int b    = blockIdx.y;
    const int mask_is_int32 = g_mask_is_int32;

    // ---- load q / q_position tiles, pre-scaled by 1/sqrt(64) = 0.125 ----
    {
        const float4* qsrc  = (const float4*)(qg  + ((size_t)b * LL + t0) * DD);
        const float4* qpsrc = (const float4*)(qpg + ((size_t)b * LL + t0) * DD);
        for (int it = tid; it < QT * 16; it += 256) {
            int r = it >> 4, c = it & 15;
            float4 a = qsrc[it];
            a.x *= 0.125f; a.y *= 0.125f; a.z *= 0.125f; a.w *= 0.125f;
            q_s4[r * KSTR + c] = a;
            float4 p = qpsrc[it];
            p.x *= 0.125f; p.y *= 0.125f; p.z *= 0.125f; p.w *= 0.125f;
            qp_s4[r * KSTR + c] = p;
        }
    }

    const int j0 = w * 8;               // this warp's key-column base within chunk
    const int jbase_off = 992 - t0;     // pdpa window base = m0 + 992 - t0

    // =================== Phase 1: scores ===================
    for (int ch = 0; ch < NCH; ch++) {
        const int m0 = ch * MC;
        __syncthreads();   // protect kv_s/pd_s/mk_s reuse from previous chunk

        // K chunk -> smem
        {
            const float4* src = (const float4*)(kg + ((size_t)b * LL + m0) * DD);
            for (int it = tid; it < MC * 16; it += 256) {
                int r = it >> 4, c = it & 15;
                kv_s4[r * KSTR + c] = src[it];
            }
        }
        // pdpa sliding window: rows [m0 + 992 - t0, +95)
        {
            const float4* src = (const float4*)(pg + ((size_t)b * (2 * LL - 1) + (m0 + jbase_off)) * DD);
            for (int it = tid; it < 95 * 16; it += 256) {
                int r = it >> 4, c = it & 15;
                pd_s4[r * KSTR + c] = src[it];
            }
        }
        // mask chunk: 32 rows x 64 entries (dtype-adaptive)
        if (mask_is_int32) {
            const int* src = (const int*)mg + ((size_t)b * LL + t0) * LL + m0;
            // 2048 entries, 8 per thread
            for (int it = tid; it < QT * MC; it += 256) {
                int r = it >> 6, c = it & 63;
                mk_s[r * 64 + c] = (unsigned char)(src[(size_t)r * LL + c] != 0);
            }
        } else {
            const unsigned long long* src =
                (const unsigned long long*)(mg + ((size_t)b * LL + t0) * LL + m0);
            int r = tid >> 3, sg = tid & 7;
            ((unsigned long long*)mk_s)[tid] = src[(size_t)r * (LL / 8) + sg];
        }
        __syncthreads();

        float acc[8];
        #pragma unroll
        for (int jj = 0; jj < 8; jj++) acc[jj] = 0.f;

        // content: q[lane] . k[j0+jj]   (q vector across lanes, k broadcast)
        #pragma unroll
        for (int dg = 0; dg < 16; dg++) {
            float4 qv = q_s4[lane * KSTR + dg];
            #pragma unroll
            for (int jj = 0; jj < 8; jj++) {
                float4 kv = kv_s4[(j0 + jj) * KSTR + dg];
                acc[jj] = fmaf(qv.x, kv.x, acc[jj]);
                acc[jj] = fmaf(qv.y, kv.y, acc[jj]);
                acc[jj] = fmaf(qv.z, kv.z, acc[jj]);
                acc[jj] = fmaf(qv.w, kv.w, acc[jj]);
            }
        }
        // positional: qpos[lane] . pdpa[31 - lane + j0 + jj]
        #pragma unroll
        for (int dg = 0; dg < 16; dg++) {
            float4 qv = qp_s4[lane * KSTR + dg];
            #pragma unroll
            for (int jj = 0; jj < 8; jj++) {
                float4 pv = pd_s4[(31 - lane + j0 + jj) * KSTR + dg];
                acc[jj] = fmaf(qv.x, pv.x, acc[jj]);
                acc[jj] = fmaf(qv.y, pv.y, acc[jj]);
                acc[jj] = fmaf(qv.z, pv.z, acc[jj]);
                acc[jj] = fmaf(qv.w, pv.w, acc[jj]);
            }
        }
        // mask + store to padded score tile
        #pragma unroll
        for (int jj = 0; jj < 8; jj++) {
            int ml = j0 + jj;
            float val = mk_s[lane * 64 + ml] ? neg_inf() : acc[jj];
            s[lane * SDIM + m0 + ml] = val;
        }
    }

    // =================== Softmax + attn writeback ===================
    __syncthreads();
    {
        float* attn_base = out + (size_t)BB * LL * DD;
        #pragma unroll
        for (int rr = 0; rr < 4; rr++) {
            int row = w * 4 + rr;
            float* srow = s + row * SDIM;

            float mx = neg_inf();
            for (int m = lane; m < LL; m += 32) mx = fmaxf(mx, srow[m]);
            #pragma unroll
            for (int o = 16; o; o >>= 1) mx = fmaxf(mx, __shfl_xor_sync(0xffffffffu, mx, o));

            float sum = 0.f;
            for (int m = lane; m < LL; m += 32) {
                float e = __expf(srow[m] - mx);
                srow[m] = e;
                sum += e;
            }
            #pragma unroll
            for (int o = 16; o; o >>= 1) sum += __shfl_xor_sync(0xffffffffu, sum, o);
            float inv = 1.0f / sum;

            float* arow = attn_base + ((size_t)b * LL + t0 + row) * LL;
            for (int m = lane; m < LL; m += 32) {
                float pval = srow[m] * inv;
                srow[m] = pval;     // keep normalized p for phase 2
                arow[m] = pval;     // emit attn
            }
        }
    }

    // =================== Phase 2: output = attn @ V ===================
    const int dq = tid & 15;   // d block: [4*dq, 4*dq+4)
    const int tp = tid >> 4;   // rows 2*tp, 2*tp+1
    float4 a0 = make_float4(0.f, 0.f, 0.f, 0.f);
    float4 a1 = make_float4(0.f, 0.f, 0.f, 0.f);

    for (int ch = 0; ch < NCH; ch++) {
        const int m0 = ch * MC;
        __syncthreads();
        {
            const float4* src = (const float4*)(vg + ((size_t)b * LL + m0) * DD);
            for (int it = tid; it < MC * 16; it += 256) {
                int r = it >> 4, c = it & 15;
                kv_s4[r * KSTR + c] = src[it];
            }
        }
        __syncthreads();

        const float* s0 = s + (2 * tp) * SDIM + m0;
        const float* s1 = s0 + SDIM;
        #pragma unroll 8
        for (int ml = 0; ml < MC; ml++) {
            float4 vv = kv_s4[ml * KSTR + dq];
            float p0 = s0[ml];
            float p1 = s1[ml];
            a0.x = fmaf(p0, vv.x, a0.x);
            a0.y = fmaf(p0, vv.y, a0.y);
            a0.z = fmaf(p0, vv.z, a0.z);
            a0.w = fmaf(p0, vv.w, a0.w);
            a1.x = fmaf(p1, vv.x, a1.x);
            a1.y = fmaf(p1, vv.y, a1.y);
            a1.z = fmaf(p1, vv.z, a1.z);
            a1.w = fmaf(p1, vv.w, a1.w);
        }
    }

    // write output rows 2*tp, 2*tp+1
    {
        float4* orow = (float4*)(out + ((size_t)b * LL + t0 + 2 * tp) * DD);
        orow[dq] = a0;
        orow[16 + dq] = a1;   // next row = +64 floats = +16 float4
    }
}

extern "C" void kernel_launch(void* const* d_in, const int* in_sizes, int n_in,
                              void* d_out, int out_size)
{
    // Locate attn_mask (B*L*L elems) and position_dpa (B*(2L-1)*D elems) by
    // size; remaining three 2M tensors + q_position keep metadata order.
    int i_mask = 3, i_pdpa = 4;
    for (int i = 0; i < n_in; i++) {
        if (in_sizes[i] == BB * LL * LL)            i_mask = i;
        else if (in_sizes[i] == BB * (2*LL-1) * DD) i_pdpa = i;
    }
    // the four [B,L,D] tensors in metadata order: q, k, v, q_position
    int small_idx[4]; int ns = 0;
    for (int i = 0; i < n_in && ns < 4; i++)
        if (i != i_mask && i != i_pdpa) small_idx[ns++] = i;

    const float*         q    = (const float*)d_in[small_idx[0]];
    const float*         k    = (const float*)d_in[small_idx[1]];
    const float*         v    = (const float*)d_in[small_idx[2]];
    const float*         qpos = (const float*)d_in[small_idx[3]];
    const unsigned char* mask = (const unsigned char*)d_in[i_mask];
    const float*         pdpa = (const float*)d_in[i_pdpa];
    float* out = (float*)d_out;

    size_t smem_bytes = (size_t)(QT * SDIM + 2 * QT * 68 + MC * 68 + 96 * 68) * sizeof(float)
                      + 2048;  // mask bytes
    cudaFuncSetAttribute(sdpa_rel_kernel,
                         cudaFuncAttributeMaxDynamicSharedMemorySize,
                         (int)smem_bytes);

    detect_mask_kernel<<<1, 32>>>(mask);
    dim3 grid(LL / QT, BB);
    sdpa_rel_kernel<<<grid, 256, smem_bytes>>>(q, k, v, mask, pdpa, qpos, out);
}

// round 4
// speedup vs baseline: 1.9567x; 1.9567x over previous
#include <cuda_runtime.h>
#include <cstddef>

#define BB 32
#define LL 1024
#define DD 64
#define QT 32
#define MC 64
#define NCH 16
#define F4S 17            // float4 row stride (68 floats)
#define FS  68            // float row stride
#define DSTR 98           // D tile float stride

// ---- smem float offsets ----
#define OFF_Q    0
#define OFF_QP   2176
#define OFF_K    4352
#define OFF_V    8704
#define OFF_PDW  13056
#define OFF_D    19584
#define OFF_P    22720
#define OFF_RED  24896
#define OFF_INV  25152
#define SMEM_FLOATS 25184

__device__ int g_mask_is_int32;
__device__ float g_inv[BB * LL];

__device__ __forceinline__ void fma2(unsigned long long& d,
                                     unsigned long long a,
                                     unsigned long long b) {
    asm("fma.rn.f32x2 %0, %1, %2, %0;" : "+l"(d) : "l"(a), "l"(b));
}
__device__ __forceinline__ unsigned long long add2(unsigned long long a,
                                                   unsigned long long b) {
    unsigned long long r;
    asm("add.rn.f32x2 %0, %1, %2;" : "=l"(r) : "l"(a), "l"(b));
    return r;
}
__device__ __forceinline__ void unpack2(unsigned long long v, float& a, float& b) {
    unsigned int lo, hi;
    asm("mov.b64 {%0,%1}, %2;" : "=r"(lo), "=r"(hi) : "l"(v));
    a = __uint_as_float(lo); b = __uint_as_float(hi);
}
__device__ __forceinline__ float hsum2(unsigned long long v) {
    float a, b; unpack2(v, a, b); return a + b;
}
__device__ __forceinline__ unsigned long long dup2(float x) {
    unsigned long long r; unsigned int xi = __float_as_uint(x);
    asm("mov.b64 %0, {%1, %1};" : "=l"(r) : "r"(xi));
    return r;
}

// Detect mask dtype: int32 (bytes at offset%4!=0 all zero) vs uint8 bool.
__global__ void detect_mask_kernel(const unsigned char* __restrict__ m)
{
    if (threadIdx.x == 0 && blockIdx.x == 0) {
        int nz = 0;
        for (int i = 0; i < 4096; i++)
            if ((i & 3) != 0 && m[i] != 0) nz++;
        g_mask_is_int32 = (nz == 0) ? 1 : 0;
    }
}

__global__ __launch_bounds__(256, 2)
void sdpa_rel_kernel(const float* __restrict__ qg,
                     const float* __restrict__ kg,
                     const float* __restrict__ vg,
                     const unsigned char* __restrict__ mg,
                     const float* __restrict__ pg,
                     const float* __restrict__ qpg,
                     float* __restrict__ out)
{
    extern __shared__ float smem[];
    float* q_s   = smem + OFF_Q;
    float* qp_s  = smem + OFF_QP;
    float* k_s   = smem + OFF_K;
    float* v_s   = smem + OFF_V;
    float* pdw_s = smem + OFF_PDW;
    float* D_s   = smem + OFF_D;
    float* p_s   = smem + OFF_P;
    float* red_s = smem + OFF_RED;
    float* inv_s = smem + OFF_INV;

    float4* q_s4   = (float4*)q_s;
    float4* qp_s4  = (float4*)qp_s;
    float4* k_s4   = (float4*)k_s;
    float4* v_s4   = (float4*)v_s;
    float4* pdw_s4 = (float4*)pdw_s;
    float4* p_s4   = (float4*)p_s;
    const ulonglong2* q_s2   = (const ulonglong2*)q_s;
    const ulonglong2* qp_s2  = (const ulonglong2*)qp_s;
    const ulonglong2* k_s2   = (const ulonglong2*)k_s;
    const ulonglong2* v_s2   = (const ulonglong2*)v_s;
    const ulonglong2* pdw_s2 = (const ulonglong2*)pdw_s;

    const int tid  = threadIdx.x;
    const int lane = tid & 31;
    const int w    = tid >> 5;
    const int dq   = lane & 15;       // phase-2 d quad
    const int half = lane >> 4;       // phase-2 ml half
    const int t0   = blockIdx.x * QT;
    const int b    = blockIdx.y;
    const int mask_is_int32 = g_mask_is_int32;

    // q / qp tiles, pre-scaled by 1/8
    {
        const float4* qsrc  = (const float4*)(qg  + ((size_t)b * LL + t0) * DD);
        const float4* qpsrc = (const float4*)(qpg + ((size_t)b * LL + t0) * DD);
        #pragma unroll
        for (int i = 0; i < 2; i++) {
            int it = tid + i * 256;
            int r = it >> 4, c = it & 15;
            float4 a = qsrc[it];
            a.x *= 0.125f; a.y *= 0.125f; a.z *= 0.125f; a.w *= 0.125f;
            q_s4[r * F4S + c] = a;
            float4 p = qpsrc[it];
            p.x *= 0.125f; p.y *= 0.125f; p.z *= 0.125f; p.w *= 0.125f;
            qp_s4[r * F4S + c] = p;
        }
    }

    const int jbase = 992 - t0;      // absolute pdpa row for local c=0 at m0=0
    const int c0 = w * 12;           // diag-GEMM column base for this warp
    const int nc = (95 - c0 < 12) ? (95 - c0) : 12;

    unsigned long long acc[4][2];    // O accumulators: 4 rows x (d pair-pairs)
    #pragma unroll
    for (int r = 0; r < 4; r++) { acc[r][0] = 0ull; acc[r][1] = 0ull; }
    float rowsum = 0.f;

    float4* attn4 = (float4*)(out + (size_t)BB * LL * DD);

    for (int ch = 0; ch < NCH; ch++) {
        const int m0 = ch * MC;
        __syncthreads();

        // ---- loads: K, V, pdpa window ----
        {
            const float4* ks = (const float4*)(kg + ((size_t)b * LL + m0) * DD);
            const float4* vs = (const float4*)(vg + ((size_t)b * LL + m0) * DD);
            #pragma unroll
            for (int i = 0; i < 4; i++) {
                int it = tid + i * 256;
                int r = it >> 4, c = it & 15;
                k_s4[r * F4S + c] = ks[it];
                v_s4[r * F4S + c] = vs[it];
            }
            const float4* ps = (const float4*)(pg + ((size_t)b * (2 * LL - 1) + (m0 + jbase)) * DD);
            for (int it = tid; it < 95 * 16; it += 256) {
                int r = it >> 4, c = it & 15;
                pdw_s4[r * F4S + c] = ps[it];
            }
        }
        // mask prefetch straight from gmem (per-thread: row=lane, cols w*8..+8)
        unsigned long long mbits = 0ull;
        uint4 ma = make_uint4(0,0,0,0), mb = make_uint4(0,0,0,0);
        if (mask_is_int32) {
            const uint4* mi = (const uint4*)((const int*)mg
                              + ((size_t)(b * LL + t0 + lane)) * LL + m0 + w * 8);
            ma = __ldg(mi); mb = __ldg(mi + 1);
        } else {
            mbits = __ldg((const unsigned long long*)(mg
                       + ((size_t)(b * LL + t0 + lane)) * LL + m0 + w * 8));
        }
        __syncthreads();

        // ---- diag GEMM: D[t=lane][c] = qp[lane] . pdw[c] ----
        {
            unsigned long long dacc[12];
            #pragma unroll
            for (int cc = 0; cc < 12; cc++) dacc[cc] = 0ull;
            #pragma unroll 4
            for (int dg = 0; dg < 16; dg++) {
                ulonglong2 qp2 = qp_s2[lane * F4S + dg];
                #pragma unroll
                for (int cc = 0; cc < 12; cc++) {
                    if (cc < nc) {
                        ulonglong2 pd2 = pdw_s2[(c0 + cc) * F4S + dg];
                        fma2(dacc[cc], qp2.x, pd2.x);
                        fma2(dacc[cc], qp2.y, pd2.y);
                    }
                }
            }
            #pragma unroll
            for (int cc = 0; cc < 12; cc++)
                if (cc < nc) D_s[lane * DSTR + c0 + cc] = hsum2(dacc[cc]);
        }

        // ---- content GEMM: rows=lane, cols=w*8+jj ----
        unsigned long long cacc[8];
        #pragma unroll
        for (int jj = 0; jj < 8; jj++) cacc[jj] = 0ull;
        #pragma unroll 4
        for (int dg = 0; dg < 16; dg++) {
            ulonglong2 q2 = q_s2[lane * F4S + dg];
            #pragma unroll
            for (int jj = 0; jj < 8; jj++) {
                ulonglong2 k2 = k_s2[(w * 8 + jj) * F4S + dg];
                fma2(cacc[jj], q2.x, k2.x);
                fma2(cacc[jj], q2.y, k2.y);
            }
        }
        __syncthreads();   // D_s visible to all

        // ---- epilogue: s = content + D, mask, exp, rowsum, p tile ----
        #pragma unroll
        for (int jj = 0; jj < 8; jj++) {
            unsigned int mraw;
            if (mask_is_int32)
                mraw = (jj < 4) ? (&ma.x)[jj] : (&mb.x)[jj - 4];
            else
                mraw = (unsigned int)((mbits >> (8 * jj)) & 0xffULL);
            float s = hsum2(cacc[jj]) + D_s[lane * DSTR + 31 - lane + w * 8 + jj];
            float p = mraw ? 0.f : __expf(s);
            rowsum += p;
            p_s[lane * FS + w * 8 + jj] = p;
        }
        __syncthreads();   // p_s ready

        // ---- attn writeback (unnormalized), coalesced from p tile ----
        #pragma unroll
        for (int i = 0; i < 2; i++) {
            int it = tid + i * 256;
            int r = it >> 4, c = it & 15;
            attn4[((size_t)(b * LL + t0 + r)) * 256 + (m0 >> 2) + c] = p_s4[r * F4S + c];
        }

        // ---- O accumulation: thread = (dq, half, w); rows w*4+rr ----
        const int rbase = w * 4;
        #pragma unroll
        for (int mlg = 0; mlg < 8; mlg++) {
            float4 pv0 = p_s4[(rbase + 0) * F4S + half * 8 + mlg];
            float4 pv1 = p_s4[(rbase + 1) * F4S + half * 8 + mlg];
            float4 pv2 = p_s4[(rbase + 2) * F4S + half * 8 + mlg];
            float4 pv3 = p_s4[(rbase + 3) * F4S + half * 8 + mlg];
            float pr0[4] = {pv0.x, pv0.y, pv0.z, pv0.w};
            float pr1[4] = {pv1.x, pv1.y, pv1.z, pv1.w};
            float pr2[4] = {pv2.x, pv2.y, pv2.z, pv2.w};
            float pr3[4] = {pv3.x, pv3.y, pv3.z, pv3.w};
            #pragma unroll
            for (int e = 0; e < 4; e++) {
                int ml = half * 32 + mlg * 4 + e;
                ulonglong2 vv = v_s2[ml * F4S + dq];
                unsigned long long p0 = dup2(pr0[e]);
                unsigned long long p1 = dup2(pr1[e]);
                unsigned long long p2 = dup2(pr2[e]);
                unsigned long long p3 = dup2(pr3[e]);
                fma2(acc[0][0], p0, vv.x); fma2(acc[0][1], p0, vv.y);
                fma2(acc[1][0], p1, vv.x); fma2(acc[1][1], p1, vv.y);
                fma2(acc[2][0], p2, vv.x); fma2(acc[2][1], p2, vv.y);
                fma2(acc[3][0], p3, vv.x); fma2(acc[3][1], p3, vv.y);
            }
        }
    }

    // ---- rowsum reduce across warps ----
    red_s[w * 32 + lane] = rowsum;
    __syncthreads();
    if (w == 0) {
        float s8 = 0.f;
        #pragma unroll
        for (int i = 0; i < 8; i++) s8 += red_s[i * 32 + lane];
        float inv = 1.0f / s8;
        inv_s[lane] = inv;
        g_inv[b * LL + t0 + lane] = inv;
    }
    __syncthreads();

    // ---- combine halves, scale, write O ----
    #pragma unroll
    for (int rr = 0; rr < 4; rr++) {
        unsigned long long s0 = add2(acc[rr][0],
                                     __shfl_xor_sync(0xffffffffu, acc[rr][0], 16));
        unsigned long long s1 = add2(acc[rr][1],
                                     __shfl_xor_sync(0xffffffffu, acc[rr][1], 16));
        if (half == 0) {
            int row = w * 4 + rr;
            float iv = inv_s[row];
            float o0, o1, o2, o3;
            unpack2(s0, o0, o1);
            unpack2(s1, o2, o3);
            float4 o = make_float4(o0 * iv, o1 * iv, o2 * iv, o3 * iv);
            ((float4*)out)[((size_t)(b * LL + t0 + row)) * 16 + dq] = o;
        }
    }
}

// Scale attn by per-row inverse sums.
__global__ __launch_bounds__(256)
void scale_attn_kernel(float* __restrict__ attn)
{
    int idx = blockIdx.x * 256 + threadIdx.x;   // float4 index
    int row = idx >> 8;                          // 256 float4 per row
    float iv = __ldg(&g_inv[row]);
    float4* a4 = (float4*)attn;
    float4 v = a4[idx];
    v.x *= iv; v.y *= iv; v.z *= iv; v.w *= iv;
    a4[idx] = v;
}

extern "C" void kernel_launch(void* const* d_in, const int* in_sizes, int n_in,
                              void* d_out, int out_size)
{
    int i_mask = 3, i_pdpa = 4;
    for (int i = 0; i < n_in; i++) {
        if (in_sizes[i] == BB * LL * LL)              i_mask = i;
        else if (in_sizes[i] == BB * (2*LL-1) * DD)   i_pdpa = i;
    }
    int small_idx[4]; int ns = 0;
    for (int i = 0; i < n_in && ns < 4; i++)
        if (i != i_mask && i != i_pdpa) small_idx[ns++] = i;

    const float*         q    = (const float*)d_in[small_idx[0]];
    const float*         k    = (const float*)d_in[small_idx[1]];
    const float*         v    = (const float*)d_in[small_idx[2]];
    const float*         qpos = (const float*)d_in[small_idx[3]];
    const unsigned char* mask = (const unsigned char*)d_in[i_mask];
    const float*         pdpa = (const float*)d_in[i_pdpa];
    float* out = (float*)d_out;

    size_t smem_bytes = (size_t)SMEM_FLOATS * sizeof(float);
    cudaFuncSetAttribute(sdpa_rel_kernel,
                         cudaFuncAttributeMaxDynamicSharedMemorySize,
                         (int)smem_bytes);

    detect_mask_kernel<<<1, 32>>>(mask);
    dim3 grid(LL / QT, BB);
    sdpa_rel_kernel<<<grid, 256, smem_bytes>>>(q, k, v, mask, pdpa, qpos, out);

    float* attn = out + (size_t)BB * LL * DD;
    scale_attn_kernel<<<(BB * LL * LL / 4) / 256, 256>>>(attn);
}